// round 1
// baseline (speedup 1.0000x reference)
#include <cuda_runtime.h>
#include <cuda_bf16.h>
#include <math.h>

// Problem constants
#define BSZ   8
#define MROW  64
#define NCOL  4096
#define KSEL  32
#define NPAIR (BSZ * MROW)        // 512 (b,m) pairs
#define NROWS (NPAIR * KSEL)      // 16384 output rows of NCOL floats

#define TPB   256
#define VPT   (NCOL / TPB)        // 16 values per thread

// Scratch: sorted-ascending top-k indices per (b,m) row. Static device array
// (no allocation allowed).
__device__ int g_idx[NROWS];

__global__ __launch_bounds__(TPB)
void topk_kernel(const float* __restrict__ logits, const float* __restrict__ u)
{
    const int bm = blockIdx.x;              // 0..511  (b*MROW + m)
    const int m  = bm & (MROW - 1);
    const float* __restrict__ urow = u      + (size_t)bm * NCOL;
    const float* __restrict__ lrow = logits + (size_t)m  * NCOL;

    const int t    = threadIdx.x;
    const int lane = t & 31;
    const int wid  = t >> 5;
    const int base = t * VPT;

    const float NEG_INF = __int_as_float(0xff800000);

    // Load + perturb: v = logits + gumbel(0, 0.001) noise, kept in registers.
    float v[VPT];
#pragma unroll
    for (int j = 0; j < VPT; j++) {
        float uu = urow[base + j];
        float gn = -0.001f * logf(-logf(uu + 1e-20f) + 1e-20f);
        v[j] = lrow[base + j] + gn;
    }

    __shared__ float s_wv[TPB / 32];
    __shared__ int   s_wi[TPB / 32];
    __shared__ int   s_best;
    __shared__ int   s_sel[KSEL];

    for (int it = 0; it < KSEL; it++) {
        // Thread-local argmax over 16 registers (tie -> lower j, loop order does this).
        float bv = v[0];
        int   bj = 0;
#pragma unroll
        for (int j = 1; j < VPT; j++) {
            if (v[j] > bv) { bv = v[j]; bj = j; }
        }
        int bi = base + bj;

        // Warp argmax (tie -> lower global index; shfl_down brings higher lanes
        // = higher indices, so strict '>' plus tie check keeps lower index).
#pragma unroll
        for (int off = 16; off > 0; off >>= 1) {
            float ov = __shfl_down_sync(0xffffffffu, bv, off);
            int   oi = __shfl_down_sync(0xffffffffu, bi, off);
            if (ov > bv || (ov == bv && oi < bi)) { bv = ov; bi = oi; }
        }
        if (lane == 0) { s_wv[wid] = bv; s_wi[wid] = bi; }
        __syncthreads();

        if (t == 0) {
            float gv = s_wv[0];
            int   gi = s_wi[0];
#pragma unroll
            for (int w = 1; w < TPB / 32; w++) {
                if (s_wv[w] > gv || (s_wv[w] == gv && s_wi[w] < gi)) {
                    gv = s_wv[w]; gi = s_wi[w];
                }
            }
            s_best   = gi;
            s_sel[it] = gi;
        }
        __syncthreads();

        // Owner thread retires the winner.
        const int gbest = s_best;
        if ((gbest >> 4) == t) {          // VPT == 16
            const int jj = gbest & (VPT - 1);
#pragma unroll
            for (int j = 0; j < VPT; j++) {
                if (j == jj) v[j] = NEG_INF;
            }
        }
        // s_best/s_sel reads complete before next iteration's writes because
        // writes happen only after the next __syncthreads().
    }

    // Rank by counting -> ascending-sorted indices (all distinct).
    if (t < KSEL) {
        const int myidx = s_sel[t];
        int rank = 0;
#pragma unroll
        for (int j = 0; j < KSEL; j++) rank += (s_sel[j] < myidx) ? 1 : 0;
        g_idx[bm * KSEL + rank] = myidx;
    }
}

// One block per output row of NCOL floats: fused memset + one-hot scatter.
// 256 threads x 4 float4 stores each = 4096 floats.
__global__ __launch_bounds__(TPB)
void fill_kernel(float* __restrict__ out)
{
    const int r = blockIdx.x;                 // 0..NROWS-1
    const int target = g_idx[r];              // column index of the single 1.0
    float4* __restrict__ o = reinterpret_cast<float4*>(out + (size_t)r * NCOL);

    const int t = threadIdx.x;
#pragma unroll
    for (int i = 0; i < 4; i++) {
        const int v4 = t + i * TPB;           // float4 slot 0..1023
        const int n0 = v4 * 4;
        float4 val;
        val.x = (target == n0    ) ? 1.0f : 0.0f;
        val.y = (target == n0 + 1) ? 1.0f : 0.0f;
        val.z = (target == n0 + 2) ? 1.0f : 0.0f;
        val.w = (target == n0 + 3) ? 1.0f : 0.0f;
        o[v4] = val;
    }
}

extern "C" void kernel_launch(void* const* d_in, const int* in_sizes, int n_in,
                              void* d_out, int out_size)
{
    const float* logits = (const float*)d_in[0];   // (64, 4096) fp32
    const float* u      = (const float*)d_in[1];   // (8, 64, 4096) fp32
    float*       out    = (float*)d_out;           // (8, 64, 32, 4096) fp32

    topk_kernel<<<NPAIR, TPB>>>(logits, u);
    fill_kernel<<<NROWS, TPB>>>(out);
}

// round 2
// speedup vs baseline: 1.1742x; 1.1742x over previous
#include <cuda_runtime.h>
#include <cuda_bf16.h>
#include <math.h>

// Problem constants
#define BSZ   8
#define MROW  64
#define NCOL  4096
#define KSEL  32
#define NPAIR (BSZ * MROW)        // 512 (b,m) pairs -> 512 blocks
#define TPB   256                 // 8 warps
#define VPT   16                  // values per thread in phase 1 (512 per warp)

// Order-preserving float->uint map: a > b  <=>  fmap(a) > fmap(b)
__device__ __forceinline__ unsigned fmap(float f) {
    unsigned b = __float_as_uint(f);
    return b ^ ((unsigned)(((int)b) >> 31) | 0x80000000u);
}

__global__ __launch_bounds__(TPB)
void dps_topk_fused(const float* __restrict__ logits,
                    const float* __restrict__ u,
                    float* __restrict__ out)
{
    const int bm   = blockIdx.x;            // 0..511
    const int m    = bm & (MROW - 1);
    const int t    = threadIdx.x;
    const int lane = t & 31;
    const int warp = t >> 5;                // 0..7

    __shared__ unsigned s_cval[TPB];        // 8 warps x 32 candidates (mapped)
    __shared__ int      s_cidx[TPB];
    __shared__ int      s_sel[KSEL];        // selection order
    __shared__ int      s_sorted[KSEL];     // ascending indices

    // ---- Load + perturb (mapped-uint domain), 16 values/thread ----
    const int base = warp * 512 + lane * VPT;
    const float4* __restrict__ u4 = (const float4*)(u + (size_t)bm * NCOL);
    const float4* __restrict__ l4 = (const float4*)(logits + (size_t)m * NCOL);
    const int p = base >> 2;

    unsigned um[VPT];
#pragma unroll
    for (int q = 0; q < 4; q++) {
        float4 uu = u4[p + q];
        float4 ll = l4[p + q];
        float g0 = -0.001f * __logf(-__logf(uu.x + 1e-20f) + 1e-20f);
        float g1 = -0.001f * __logf(-__logf(uu.y + 1e-20f) + 1e-20f);
        float g2 = -0.001f * __logf(-__logf(uu.z + 1e-20f) + 1e-20f);
        float g3 = -0.001f * __logf(-__logf(uu.w + 1e-20f) + 1e-20f);
        um[q * 4 + 0] = fmap(ll.x + g0);
        um[q * 4 + 1] = fmap(ll.y + g1);
        um[q * 4 + 2] = fmap(ll.z + g2);
        um[q * 4 + 3] = fmap(ll.w + g3);
    }

    // ---- Phase 1: each warp -> its local top-32 (no block syncs) ----
    const unsigned FULL = 0xffffffffu;
    for (int it = 0; it < KSEL; it++) {
        unsigned lm = um[0];
#pragma unroll
        for (int j = 1; j < VPT; j++) lm = max(lm, um[j]);
        const unsigned w = __reduce_max_sync(FULL, lm);

        // lowest local slot holding w (descending scan -> lowest j wins)
        int myj = VPT;
#pragma unroll
        for (int j = VPT - 1; j >= 0; j--) if (um[j] == w) myj = j;

        const unsigned bal = __ballot_sync(FULL, myj < VPT);
        const int src  = __ffs(bal) - 1;                     // lowest lane = lowest index
        const int widx = __shfl_sync(FULL, base + myj, src);

        if (lane == 0) { s_cval[warp * KSEL + it] = w; s_cidx[warp * KSEL + it] = widx; }
        if (lane == src) {
#pragma unroll
            for (int j = 0; j < VPT; j++) if (j == myj) um[j] = 0u;
        }
    }
    __syncthreads();

    // ---- Phase 2: warp 0 merges 256 candidates -> global top-32 ----
    if (warp == 0) {
        unsigned cv[8];
        int      ci[8];
#pragma unroll
        for (int j = 0; j < 8; j++) {
            cv[j] = s_cval[lane * 8 + j];
            ci[j] = s_cidx[lane * 8 + j];
        }
        for (int it = 0; it < KSEL; it++) {
            unsigned lm = cv[0];
#pragma unroll
            for (int j = 1; j < 8; j++) lm = max(lm, cv[j]);
            const unsigned w = __reduce_max_sync(FULL, lm);

            int myj = 8;
            int myi = 0;
#pragma unroll
            for (int j = 7; j >= 0; j--) if (cv[j] == w) { myj = j; myi = ci[j]; }

            const unsigned bal = __ballot_sync(FULL, myj < 8);
            const int src  = __ffs(bal) - 1;
            const int widx = __shfl_sync(FULL, myi, src);

            if (lane == 0) s_sel[it] = widx;
            if (lane == src) {
#pragma unroll
                for (int j = 0; j < 8; j++) if (j == myj) cv[j] = 0u;
            }
        }
        __syncwarp();
        // rank-by-counting -> ascending sorted indices (all distinct)
        {
            const int myidx = s_sel[lane];
            int rank = 0;
#pragma unroll
            for (int j = 0; j < KSEL; j++) rank += (s_sel[j] < myidx) ? 1 : 0;
            s_sorted[rank] = myidx;
        }
    }
    __syncthreads();

    // ---- Store phase: 32 rows x 4096 floats, fused memset + one-hot ----
    float* __restrict__ bout = out + (size_t)bm * (KSEL * NCOL);
#pragma unroll 4
    for (int rr = 0; rr < KSEL; rr++) {
        const int target = s_sorted[rr];
        float4* __restrict__ o = (float4*)(bout + rr * NCOL);
#pragma unroll
        for (int i = 0; i < 4; i++) {
            const int slot = t + i * TPB;      // float4 slot 0..1023
            const int n0 = slot * 4;
            float4 val;
            val.x = (target == n0    ) ? 1.0f : 0.0f;
            val.y = (target == n0 + 1) ? 1.0f : 0.0f;
            val.z = (target == n0 + 2) ? 1.0f : 0.0f;
            val.w = (target == n0 + 3) ? 1.0f : 0.0f;
            o[slot] = val;
        }
    }
}

extern "C" void kernel_launch(void* const* d_in, const int* in_sizes, int n_in,
                              void* d_out, int out_size)
{
    const float* logits = (const float*)d_in[0];   // (64, 4096) fp32
    const float* u      = (const float*)d_in[1];   // (8, 64, 4096) fp32
    float*       out    = (float*)d_out;           // (8, 64, 32, 4096) fp32

    dps_topk_fused<<<NPAIR, TPB>>>(logits, u, out);
}

// round 3
// speedup vs baseline: 1.2050x; 1.0262x over previous
#include <cuda_runtime.h>
#include <cuda_bf16.h>
#include <math.h>

// Problem constants
#define BSZ   8
#define MROW  64
#define NCOL  4096
#define KSEL  32
#define NPAIR (BSZ * MROW)        // 512 (b,m) pairs
#define NROWS (NPAIR * KSEL)      // 16384 output rows
#define TPB   256                 // 8 warps
#define VPT   16                  // values/thread in topk (512 per warp)

// Sorted-ascending top-k indices per (b,m). Static scratch (no allocation).
__device__ int g_idx[NROWS];

// Order-preserving float->uint map: a > b  <=>  fmap(a) > fmap(b)
__device__ __forceinline__ unsigned fmap(float f) {
    unsigned b = __float_as_uint(f);
    return b ^ ((unsigned)(((int)b) >> 31) | 0x80000000u);
}

__global__ __launch_bounds__(TPB)
void topk_kernel(const float* __restrict__ logits, const float* __restrict__ u)
{
    const int bm   = blockIdx.x;            // 0..511
    const int m    = bm & (MROW - 1);
    const int t    = threadIdx.x;
    const int lane = t & 31;
    const int warp = t >> 5;                // 0..7

    __shared__ unsigned s_cval[TPB];        // 8 warps x 32 candidates (mapped)
    __shared__ int      s_cidx[TPB];
    __shared__ int      s_sel[KSEL];

    // ---- Load + perturb into mapped-uint domain, 16 values/thread ----
    const int base = warp * 512 + lane * VPT;
    const float4* __restrict__ u4 = (const float4*)(u + (size_t)bm * NCOL);
    const float4* __restrict__ l4 = (const float4*)(logits + (size_t)m * NCOL);
    const int p = base >> 2;

    unsigned um[VPT];
#pragma unroll
    for (int q = 0; q < 4; q++) {
        float4 uu = u4[p + q];
        float4 ll = l4[p + q];
        float g0 = -0.001f * __logf(-__logf(uu.x + 1e-20f) + 1e-20f);
        float g1 = -0.001f * __logf(-__logf(uu.y + 1e-20f) + 1e-20f);
        float g2 = -0.001f * __logf(-__logf(uu.z + 1e-20f) + 1e-20f);
        float g3 = -0.001f * __logf(-__logf(uu.w + 1e-20f) + 1e-20f);
        um[q * 4 + 0] = fmap(ll.x + g0);
        um[q * 4 + 1] = fmap(ll.y + g1);
        um[q * 4 + 2] = fmap(ll.z + g2);
        um[q * 4 + 3] = fmap(ll.w + g3);
    }

    // ---- Phase 1: each warp -> its local top-32 (no block syncs) ----
    const unsigned FULL = 0xffffffffu;
    for (int it = 0; it < KSEL; it++) {
        unsigned lm = um[0];
#pragma unroll
        for (int j = 1; j < VPT; j++) lm = max(lm, um[j]);
        const unsigned w = __reduce_max_sync(FULL, lm);

        int myj = VPT;                       // lowest local slot holding w
#pragma unroll
        for (int j = VPT - 1; j >= 0; j--) if (um[j] == w) myj = j;

        const unsigned bal = __ballot_sync(FULL, myj < VPT);
        const int src  = __ffs(bal) - 1;     // lowest lane = lowest global index
        const int widx = __shfl_sync(FULL, base + myj, src);

        if (lane == 0) { s_cval[warp * KSEL + it] = w; s_cidx[warp * KSEL + it] = widx; }
        if (lane == src) {
#pragma unroll
            for (int j = 0; j < VPT; j++) if (j == myj) um[j] = 0u;
        }
    }
    __syncthreads();

    // ---- Phase 2: warp 0 merges 256 candidates -> global top-32 ----
    if (warp == 0) {
        unsigned cv[8];
        int      ci[8];
#pragma unroll
        for (int j = 0; j < 8; j++) {
            cv[j] = s_cval[lane * 8 + j];
            ci[j] = s_cidx[lane * 8 + j];
        }
        for (int it = 0; it < KSEL; it++) {
            unsigned lm = cv[0];
#pragma unroll
            for (int j = 1; j < 8; j++) lm = max(lm, cv[j]);
            const unsigned w = __reduce_max_sync(FULL, lm);

            int myj = 8, myi = 0;
#pragma unroll
            for (int j = 7; j >= 0; j--) if (cv[j] == w) { myj = j; myi = ci[j]; }

            const unsigned bal = __ballot_sync(FULL, myj < 8);
            const int src  = __ffs(bal) - 1;
            const int widx = __shfl_sync(FULL, myi, src);

            if (lane == 0) s_sel[it] = widx;
            if (lane == src) {
#pragma unroll
                for (int j = 0; j < 8; j++) if (j == myj) cv[j] = 0u;
            }
        }
        __syncwarp();
        // rank-by-counting -> ascending sorted order (all indices distinct)
        {
            const int myidx = s_sel[lane];
            int rank = 0;
#pragma unroll
            for (int j = 0; j < KSEL; j++) rank += (s_sel[j] < myidx) ? 1 : 0;
            g_idx[bm * KSEL + rank] = myidx;
        }
    }
}

// One block per output row: fused memset + one-hot, streaming stores.
__global__ __launch_bounds__(TPB)
void fill_kernel(float* __restrict__ out)
{
    const int r = blockIdx.x;                 // 0..NROWS-1
    const int target = g_idx[r];
    float4* __restrict__ o = reinterpret_cast<float4*>(out + (size_t)r * NCOL);

    const int t = threadIdx.x;
#pragma unroll
    for (int i = 0; i < 4; i++) {
        const int slot = t + i * TPB;         // float4 slot 0..1023
        const int n0 = slot * 4;
        float4 val;
        val.x = (target == n0    ) ? 1.0f : 0.0f;
        val.y = (target == n0 + 1) ? 1.0f : 0.0f;
        val.z = (target == n0 + 2) ? 1.0f : 0.0f;
        val.w = (target == n0 + 3) ? 1.0f : 0.0f;
        __stcs(&o[slot], val);                // streaming: don't pollute L2
    }
}

extern "C" void kernel_launch(void* const* d_in, const int* in_sizes, int n_in,
                              void* d_out, int out_size)
{
    const float* logits = (const float*)d_in[0];   // (64, 4096) fp32
    const float* u      = (const float*)d_in[1];   // (8, 64, 4096) fp32
    float*       out    = (float*)d_out;           // (8, 64, 32, 4096) fp32

    topk_kernel<<<NPAIR, TPB>>>(logits, u);
    fill_kernel<<<NROWS, TPB>>>(out);
}